// round 1
// baseline (speedup 1.0000x reference)
#include <cuda_runtime.h>
#include <math.h>

#define B_ 2
#define S_ 2048
#define H_ 16
#define D_ 64
#define E_ 1024
#define M_ (B_*S_)

// Scratch (allocation-free): q,k,v in [B,H,S,D]; attn out in [B,S,E]
__device__ float g_q[B_*H_*S_*D_];
__device__ float g_k[B_*H_*S_*D_];
__device__ float g_v[B_*H_*S_*D_];
__device__ float g_attn[(size_t)B_*S_*E_];

// ---------------------------------------------------------------------------
// GEMM: C[m,n] = sum_k A[m,k]*W[n,k] + bias[n]   (NT layout: both K-contiguous)
// MODE 0: write out[m*E_+n]                  (final projection -> d_out)
// MODE 1: apply RoPE, write [B,H,S,D]        (Q,K)
// MODE 2: no RoPE, write [B,H,S,D]           (V)
// Tile: 128x128x16, 256 threads, 8x8 per thread.
// ---------------------------------------------------------------------------
template<int MODE>
__global__ __launch_bounds__(256) void gemm_kernel(
    const float* __restrict__ A, const float* __restrict__ W,
    const float* __restrict__ bias, float* __restrict__ out)
{
    __shared__ float As[16][132];   // [k][m], pitch 132 (16B aligned, conflict-light)
    __shared__ float Bs[16][132];   // [k][n]
    const int tid = threadIdx.x;
    const int tx = tid & 15, ty = tid >> 4;
    const int m0 = blockIdx.y * 128, n0 = blockIdx.x * 128;

    float acc[8][8];
    #pragma unroll
    for (int i = 0; i < 8; i++)
        #pragma unroll
        for (int j = 0; j < 8; j++) acc[i][j] = 0.f;

    for (int k0 = 0; k0 < E_; k0 += 16) {
        #pragma unroll
        for (int it = 0; it < 2; it++) {
            int id  = tid + it * 256;
            int row = id >> 2;
            int f   = (id & 3) * 4;
            float4 a = *(const float4*)(A + (size_t)(m0 + row) * E_ + k0 + f);
            As[f+0][row] = a.x; As[f+1][row] = a.y; As[f+2][row] = a.z; As[f+3][row] = a.w;
            float4 w = *(const float4*)(W + (size_t)(n0 + row) * E_ + k0 + f);
            Bs[f+0][row] = w.x; Bs[f+1][row] = w.y; Bs[f+2][row] = w.z; Bs[f+3][row] = w.w;
        }
        __syncthreads();
        #pragma unroll
        for (int kk = 0; kk < 16; kk++) {
            float a[8], b[8];
            *(float4*)(a)     = *(const float4*)&As[kk][ty*8];
            *(float4*)(a + 4) = *(const float4*)&As[kk][ty*8 + 4];
            *(float4*)(b)     = *(const float4*)&Bs[kk][tx*8];
            *(float4*)(b + 4) = *(const float4*)&Bs[kk][tx*8 + 4];
            #pragma unroll
            for (int i = 0; i < 8; i++)
                #pragma unroll
                for (int j = 0; j < 8; j++)
                    acc[i][j] += a[i] * b[j];
        }
        __syncthreads();
    }

    // ---- epilogue ----
    #pragma unroll
    for (int i = 0; i < 8; i++) {
        int m  = m0 + ty * 8 + i;
        int bb = m >> 11;            // m / S_
        int sp = m & (S_ - 1);       // sequence position
        if (MODE == 0) {
            #pragma unroll
            for (int j = 0; j < 8; j += 4) {
                int n = n0 + tx * 8 + j;
                float4 v;
                v.x = acc[i][j]   + bias[n];
                v.y = acc[i][j+1] + bias[n+1];
                v.z = acc[i][j+2] + bias[n+2];
                v.w = acc[i][j+3] + bias[n+3];
                *(float4*)(out + (size_t)m * E_ + n) = v;
            }
        } else {
            #pragma unroll
            for (int j = 0; j < 8; j += 2) {
                int n = n0 + tx * 8 + j;
                int h = n >> 6, d = n & 63;     // d is even
                float v0 = acc[i][j]   + bias[n];
                float v1 = acc[i][j+1] + bias[n+1];
                float o0 = v0, o1 = v1;
                if (MODE == 1) {
                    // theta_d = pos * 10000^{-(2*(d mod 32))/64}
                    float e0 = (float)(2 * (d & 31)) * (1.0f / 64.0f);
                    float e1 = (float)(2 * ((d + 1) & 31)) * (1.0f / 64.0f);
                    float inv0 = 1.0f / powf(10000.0f, e0);
                    float inv1 = 1.0f / powf(10000.0f, e1);
                    float c0, s0, c1, s1;
                    sincosf((float)sp * inv0, &s0, &c0);
                    sincosf((float)sp * inv1, &s1, &c1);
                    // rot[d] = -x[d+1], rot[d+1] = x[d]
                    o0 = v0 * c0 - v1 * s0;
                    o1 = v1 * c1 + v0 * s1;
                }
                size_t base = (((size_t)(bb * H_ + h)) * S_ + sp) * D_ + d;
                out[base]     = o0;
                out[base + 1] = o1;
            }
        }
    }
}

// ---------------------------------------------------------------------------
// Flash attention (fp32): per block 64 query rows of one (b,h).
// 256 threads = 16x16; each thread owns 4 rows x 4 cols.
// Streams over key tiles of 64, online softmax, O accumulated in regs.
// Writes [B,S,H,D] (= [B,S,E]) so the output GEMM reads it directly.
// ---------------------------------------------------------------------------
__global__ __launch_bounds__(256) void attn_kernel(float* __restrict__ outbuf)
{
    extern __shared__ float sm[];
    float* Qs = sm;                  // 64 x 64
    float* Ks = Qs + 64 * 64;        // 64 x 68 (pitch 68 keeps float4 alignment)
    float* Vs = Ks + 64 * 68;        // 64 x 64
    float* Ps = Vs + 64 * 64;        // 64 x 68

    const int tid = threadIdx.x;
    const int tx = tid & 15, ty = tid >> 4;
    const int q0 = blockIdx.x * 64;
    const int h  = blockIdx.y;
    const int bb = blockIdx.z;
    const size_t head_base = ((size_t)(bb * H_ + h)) * S_ * D_;

    // load Q tile (64 rows x 64 floats)
    #pragma unroll
    for (int it = 0; it < 4; it++) {
        int id  = tid + it * 256;
        int row = id >> 4, f = (id & 15) * 4;
        float4 v = *(const float4*)(g_q + head_base + (size_t)(q0 + row) * D_ + f);
        *(float4*)&Qs[row * 64 + f] = v;
    }

    float m_i[4], l_i[4], acc[4][4];
    #pragma unroll
    for (int i = 0; i < 4; i++) {
        m_i[i] = -1e30f; l_i[i] = 0.f;
        #pragma unroll
        for (int j = 0; j < 4; j++) acc[i][j] = 0.f;
    }

    for (int kt = 0; kt < S_; kt += 64) {
        __syncthreads();   // previous PV done reading Ks/Vs/Ps
        #pragma unroll
        for (int it = 0; it < 4; it++) {
            int id  = tid + it * 256;
            int row = id >> 4, f = (id & 15) * 4;
            float4 kv = *(const float4*)(g_k + head_base + (size_t)(kt + row) * D_ + f);
            Ks[row*68 + f+0] = kv.x; Ks[row*68 + f+1] = kv.y;
            Ks[row*68 + f+2] = kv.z; Ks[row*68 + f+3] = kv.w;
            float4 vv = *(const float4*)(g_v + head_base + (size_t)(kt + row) * D_ + f);
            *(float4*)&Vs[row * 64 + f] = vv;
        }
        __syncthreads();

        // S = (Q K^T) / 8
        float sreg[4][4];
        #pragma unroll
        for (int i = 0; i < 4; i++)
            #pragma unroll
            for (int j = 0; j < 4; j++) sreg[i][j] = 0.f;

        #pragma unroll
        for (int kf = 0; kf < 16; kf++) {
            float4 q4[4], k4[4];
            #pragma unroll
            for (int i = 0; i < 4; i++) q4[i] = *(const float4*)&Qs[(ty*4 + i) * 64 + kf*4];
            #pragma unroll
            for (int j = 0; j < 4; j++) k4[j] = *(const float4*)&Ks[(tx*4 + j) * 68 + kf*4];
            #pragma unroll
            for (int i = 0; i < 4; i++)
                #pragma unroll
                for (int j = 0; j < 4; j++)
                    sreg[i][j] += q4[i].x*k4[j].x + q4[i].y*k4[j].y
                                + q4[i].z*k4[j].z + q4[i].w*k4[j].w;
        }

        // online softmax (row reductions across the 16 tx lanes)
        #pragma unroll
        for (int i = 0; i < 4; i++) {
            float mx = -1e30f;
            #pragma unroll
            for (int j = 0; j < 4; j++) {
                sreg[i][j] *= 0.125f;
                mx = fmaxf(mx, sreg[i][j]);
            }
            #pragma unroll
            for (int o = 8; o >= 1; o >>= 1)
                mx = fmaxf(mx, __shfl_xor_sync(0xffffffffu, mx, o));
            float mnew = fmaxf(m_i[i], mx);
            float corr = __expf(m_i[i] - mnew);
            m_i[i] = mnew;
            float sum = 0.f;
            #pragma unroll
            for (int j = 0; j < 4; j++) {
                float p = __expf(sreg[i][j] - mnew);
                sreg[i][j] = p;
                sum += p;
            }
            #pragma unroll
            for (int o = 8; o >= 1; o >>= 1)
                sum += __shfl_xor_sync(0xffffffffu, sum, o);
            l_i[i] = l_i[i] * corr + sum;
            #pragma unroll
            for (int j = 0; j < 4; j++) acc[i][j] *= corr;
            *(float4*)&Ps[(ty*4 + i) * 68 + tx*4] =
                make_float4(sreg[i][0], sreg[i][1], sreg[i][2], sreg[i][3]);
        }
        __syncthreads();

        // O += P V
        #pragma unroll 4
        for (int k = 0; k < 64; k++) {
            float4 v4 = *(const float4*)&Vs[k * 64 + tx*4];
            #pragma unroll
            for (int i = 0; i < 4; i++) {
                float p = Ps[(ty*4 + i) * 68 + k];
                acc[i][0] += p * v4.x; acc[i][1] += p * v4.y;
                acc[i][2] += p * v4.z; acc[i][3] += p * v4.w;
            }
        }
    }

    // normalize and write [B,S,H,D]
    #pragma unroll
    for (int i = 0; i < 4; i++) {
        float inv = 1.0f / l_i[i];
        float4 o = make_float4(acc[i][0]*inv, acc[i][1]*inv, acc[i][2]*inv, acc[i][3]*inv);
        size_t idx = (((size_t)bb * S_ + q0 + ty*4 + i) * H_ + h) * D_ + tx*4;
        *(float4*)&outbuf[idx] = o;
    }
}

// ---------------------------------------------------------------------------
extern "C" void kernel_launch(void* const* d_in, const int* in_sizes, int n_in,
                              void* d_out, int out_size)
{
    const float* x  = (const float*)d_in[0];
    const float* Wq = (const float*)d_in[1];
    const float* bq = (const float*)d_in[2];
    const float* Wk = (const float*)d_in[3];
    const float* bk = (const float*)d_in[4];
    const float* Wv = (const float*)d_in[5];
    const float* bv = (const float*)d_in[6];
    const float* Wo = (const float*)d_in[7];
    const float* bo = (const float*)d_in[8];
    float* out = (float*)d_out;

    float *pq, *pk, *pv, *pa;
    cudaGetSymbolAddress((void**)&pq, g_q);
    cudaGetSymbolAddress((void**)&pk, g_k);
    cudaGetSymbolAddress((void**)&pv, g_v);
    cudaGetSymbolAddress((void**)&pa, g_attn);

    const int smem_attn = (64*64 + 64*68 + 64*64 + 64*68) * sizeof(float); // 67584
    cudaFuncSetAttribute(attn_kernel, cudaFuncAttributeMaxDynamicSharedMemorySize, smem_attn);

    dim3 gg(E_/128, M_/128);   // (8, 32)
    gemm_kernel<1><<<gg, 256>>>(x,  Wq, bq, pq);
    gemm_kernel<1><<<gg, 256>>>(x,  Wk, bk, pk);
    gemm_kernel<2><<<gg, 256>>>(x,  Wv, bv, pv);
    attn_kernel<<<dim3(S_/64, H_, B_), 256, smem_attn>>>(pa);
    gemm_kernel<0><<<gg, 256>>>(pa, Wo, bo, out);
}

// round 2
// speedup vs baseline: 3.6367x; 3.6367x over previous
#include <cuda_runtime.h>
#include <math.h>

#define B_ 2
#define S_ 2048
#define H_ 16
#define D_ 64
#define E_ 1024
#define M_ (B_*S_)

// Scratch (allocation-free)
__device__ float g_q[B_*H_*S_*D_];
__device__ float g_k[B_*H_*S_*D_];
__device__ float g_v[B_*H_*S_*D_];
__device__ float g_attn[(size_t)B_*S_*E_];
__device__ float g_cos[S_*D_];
__device__ float g_sin[S_*D_];

// ---------------------------------------------------------------------------
// helpers
// ---------------------------------------------------------------------------
__device__ __forceinline__ unsigned f2tf(float x) {
    unsigned r;
    asm("cvt.rna.tf32.f32 %0, %1;" : "=r"(r) : "f"(x));
    return r;
}

__device__ __forceinline__ void mma_tf32(float c[4], const unsigned a[4], const unsigned b[2]) {
    asm volatile(
        "mma.sync.aligned.m16n8k8.row.col.f32.tf32.tf32.f32 "
        "{%0,%1,%2,%3},{%4,%5,%6,%7},{%8,%9},{%0,%1,%2,%3};\n"
        : "+f"(c[0]), "+f"(c[1]), "+f"(c[2]), "+f"(c[3])
        : "r"(a[0]), "r"(a[1]), "r"(a[2]), "r"(a[3]), "r"(b[0]), "r"(b[1]));
}

// ---------------------------------------------------------------------------
// RoPE table: cos/sin for all (pos, d)
// ---------------------------------------------------------------------------
__global__ void rope_table_kernel() {
    int idx = blockIdx.x * blockDim.x + threadIdx.x;   // sp*64 + d
    if (idx >= S_ * D_) return;
    int sp = idx >> 6, d = idx & 63;
    float e = (float)(2 * (d & 31)) * (1.0f / 64.0f);
    float inv = powf(10000.0f, -e);
    float s, c;
    sincosf((float)sp * inv, &s, &c);
    g_cos[idx] = c;
    g_sin[idx] = s;
}

// ---------------------------------------------------------------------------
// tf32 tensor-core GEMM: C[m,n] = sum_k A[m,k]*W[n,k] + bias[n]
// MODE 0: out[m*E+n]; MODE 1: RoPE -> [B,H,S,D]; MODE 2: -> [B,H,S,D]
// 128x128x32 tile, 256 threads (8 warps), warp tile 32x64 (2x8 mma tiles)
// ---------------------------------------------------------------------------
template<int MODE>
__global__ __launch_bounds__(256) void gemm_tc(
    const float* __restrict__ A, const float* __restrict__ W,
    const float* __restrict__ bias, float* __restrict__ out)
{
    __shared__ unsigned As[128][36];   // [row][k], pitch 36: conflict-free frags
    __shared__ unsigned Bs[128][36];   // [n][k]
    const int tid = threadIdx.x;
    const int lane = tid & 31, wid = tid >> 5;
    const int warp_m = wid >> 1, warp_n = wid & 1;
    const int m0 = blockIdx.y * 128, n0 = blockIdx.x * 128;
    const int lq = lane >> 2, lr = lane & 3;   // quad id / lane-in-quad

    float c[2][8][4];
    #pragma unroll
    for (int mt = 0; mt < 2; mt++)
        #pragma unroll
        for (int nt = 0; nt < 8; nt++)
            #pragma unroll
            for (int i = 0; i < 4; i++) c[mt][nt][i] = 0.f;

    for (int k0 = 0; k0 < E_; k0 += 32) {
        #pragma unroll
        for (int it = 0; it < 4; it++) {
            int id = tid + it * 256;
            int row = id >> 3, f = (id & 7) * 4;
            float4 a4 = *(const float4*)(A + (size_t)(m0 + row) * E_ + k0 + f);
            uint4 u;
            u.x = f2tf(a4.x); u.y = f2tf(a4.y); u.z = f2tf(a4.z); u.w = f2tf(a4.w);
            *(uint4*)&As[row][f] = u;
            float4 w4 = *(const float4*)(W + (size_t)(n0 + row) * E_ + k0 + f);
            uint4 v;
            v.x = f2tf(w4.x); v.y = f2tf(w4.y); v.z = f2tf(w4.z); v.w = f2tf(w4.w);
            *(uint4*)&Bs[row][f] = v;
        }
        __syncthreads();
        #pragma unroll
        for (int kk = 0; kk < 4; kk++) {
            int koff = kk * 8;
            unsigned bfr[8][2];
            #pragma unroll
            for (int nt = 0; nt < 8; nt++) {
                int nc = warp_n * 64 + nt * 8 + lq;
                bfr[nt][0] = Bs[nc][koff + lr];
                bfr[nt][1] = Bs[nc][koff + 4 + lr];
            }
            unsigned afr[2][4];
            #pragma unroll
            for (int mt = 0; mt < 2; mt++) {
                int mr = warp_m * 32 + mt * 16 + lq;
                afr[mt][0] = As[mr][koff + lr];
                afr[mt][1] = As[mr + 8][koff + lr];
                afr[mt][2] = As[mr][koff + 4 + lr];
                afr[mt][3] = As[mr + 8][koff + 4 + lr];
            }
            #pragma unroll
            for (int mt = 0; mt < 2; mt++)
                #pragma unroll
                for (int nt = 0; nt < 8; nt++)
                    mma_tf32(c[mt][nt], afr[mt], bfr[nt]);
        }
        __syncthreads();
    }

    // epilogue
    #pragma unroll
    for (int mt = 0; mt < 2; mt++) {
        #pragma unroll
        for (int rh = 0; rh < 2; rh++) {
            int m = m0 + warp_m * 32 + mt * 16 + lq + rh * 8;
            int bb = m >> 11, sp = m & (S_ - 1);
            #pragma unroll
            for (int nt = 0; nt < 8; nt++) {
                int n = n0 + warp_n * 64 + nt * 8 + lr * 2;
                float2 bi = *(const float2*)(bias + n);
                float v0 = c[mt][nt][rh * 2]     + bi.x;
                float v1 = c[mt][nt][rh * 2 + 1] + bi.y;
                if (MODE == 0) {
                    *(float2*)(out + (size_t)m * E_ + n) = make_float2(v0, v1);
                } else {
                    int h = n >> 6, d = n & 63;   // d even
                    float o0 = v0, o1 = v1;
                    if (MODE == 1) {
                        float2 cs = *(const float2*)(g_cos + sp * D_ + d);
                        float2 sn = *(const float2*)(g_sin + sp * D_ + d);
                        o0 = v0 * cs.x - v1 * sn.x;
                        o1 = v1 * cs.y + v0 * sn.y;
                    }
                    size_t base = (((size_t)(bb * H_ + h)) * S_ + sp) * D_ + d;
                    *(float2*)(out + base) = make_float2(o0, o1);
                }
            }
        }
    }
}

// ---------------------------------------------------------------------------
// Flash attention with tf32 mma. 128 threads (4 warps); Q tile 64 rows,
// warp owns 16 rows. K/V tiles 64. Online softmax in C-fragment registers.
// ---------------------------------------------------------------------------
__global__ __launch_bounds__(128) void attn_tc(float* __restrict__ outbuf)
{
    extern __shared__ unsigned smu[];
    unsigned (*Qs)[68] = (unsigned(*)[68])smu;            // 64 x 68
    unsigned (*Ks)[68] = (unsigned(*)[68])(smu + 64*68);  // 64 x 68
    unsigned (*Vs)[68] = (unsigned(*)[68])(smu + 2*64*68);
    unsigned (*Ps)[68] = (unsigned(*)[68])(smu + 3*64*68);

    const int tid = threadIdx.x;
    const int lane = tid & 31, wid = tid >> 5;
    const int lq = lane >> 2, lr = lane & 3;
    const int wr = wid * 16;                     // warp's first Q row in tile
    const int q0 = blockIdx.x * 64;
    const int h = blockIdx.y, bb = blockIdx.z;
    const size_t head_base = ((size_t)(bb * H_ + h)) * S_ * D_;

    // load + convert Q tile
    #pragma unroll
    for (int it = 0; it < 8; it++) {
        int id = tid + it * 128;
        int row = id >> 4, f = (id & 15) * 4;
        float4 v = *(const float4*)(g_q + head_base + (size_t)(q0 + row) * D_ + f);
        uint4 u;
        u.x = f2tf(v.x); u.y = f2tf(v.y); u.z = f2tf(v.z); u.w = f2tf(v.w);
        *(uint4*)&Qs[row][f] = u;
    }

    float o[8][4];
    float m_i[2] = {-1e30f, -1e30f}, l_i[2] = {0.f, 0.f};
    #pragma unroll
    for (int nt = 0; nt < 8; nt++)
        #pragma unroll
        for (int i = 0; i < 4; i++) o[nt][i] = 0.f;

    for (int kt = 0; kt < S_; kt += 64) {
        __syncthreads();
        #pragma unroll
        for (int it = 0; it < 8; it++) {
            int id = tid + it * 128;
            int row = id >> 4, f = (id & 15) * 4;
            float4 kv = *(const float4*)(g_k + head_base + (size_t)(kt + row) * D_ + f);
            uint4 u;
            u.x = f2tf(kv.x); u.y = f2tf(kv.y); u.z = f2tf(kv.z); u.w = f2tf(kv.w);
            *(uint4*)&Ks[row][f] = u;
            float4 vv = *(const float4*)(g_v + head_base + (size_t)(kt + row) * D_ + f);
            uint4 w;
            w.x = f2tf(vv.x); w.y = f2tf(vv.y); w.z = f2tf(vv.z); w.w = f2tf(vv.w);
            *(uint4*)&Vs[row][f] = w;
        }
        __syncthreads();

        // S = Q K^T  (M=16 rows, N=64 keys, K=64 dims)
        float s[8][4];
        #pragma unroll
        for (int nt = 0; nt < 8; nt++)
            #pragma unroll
            for (int i = 0; i < 4; i++) s[nt][i] = 0.f;

        #pragma unroll
        for (int kk = 0; kk < 8; kk++) {
            int koff = kk * 8;
            unsigned afr[4];
            afr[0] = Qs[wr + lq][koff + lr];
            afr[1] = Qs[wr + lq + 8][koff + lr];
            afr[2] = Qs[wr + lq][koff + 4 + lr];
            afr[3] = Qs[wr + lq + 8][koff + 4 + lr];
            #pragma unroll
            for (int nt = 0; nt < 8; nt++) {
                unsigned bfr[2];
                bfr[0] = Ks[nt * 8 + lq][koff + lr];
                bfr[1] = Ks[nt * 8 + lq][koff + 4 + lr];
                mma_tf32(s[nt], afr, bfr);
            }
        }

        // online softmax; thread rows: r0 = lq (c0,c1), r1 = lq+8 (c2,c3)
        #pragma unroll
        for (int rh = 0; rh < 2; rh++) {
            float mx = -1e30f;
            #pragma unroll
            for (int nt = 0; nt < 8; nt++) {
                s[nt][rh*2]   *= 0.125f;
                s[nt][rh*2+1] *= 0.125f;
                mx = fmaxf(mx, fmaxf(s[nt][rh*2], s[nt][rh*2+1]));
            }
            mx = fmaxf(mx, __shfl_xor_sync(0xffffffffu, mx, 1));
            mx = fmaxf(mx, __shfl_xor_sync(0xffffffffu, mx, 2));
            float mnew = fmaxf(m_i[rh], mx);
            float corr = __expf(m_i[rh] - mnew);
            m_i[rh] = mnew;
            float sum = 0.f;
            #pragma unroll
            for (int nt = 0; nt < 8; nt++) {
                float p0 = __expf(s[nt][rh*2]   - mnew);
                float p1 = __expf(s[nt][rh*2+1] - mnew);
                s[nt][rh*2] = p0; s[nt][rh*2+1] = p1;
                sum += p0 + p1;
            }
            sum += __shfl_xor_sync(0xffffffffu, sum, 1);
            sum += __shfl_xor_sync(0xffffffffu, sum, 2);
            l_i[rh] = l_i[rh] * corr + sum;
            #pragma unroll
            for (int nt = 0; nt < 8; nt++) {
                o[nt][rh*2]   *= corr;
                o[nt][rh*2+1] *= corr;
            }
        }

        // write P (tf32) to smem — warp-private rows
        #pragma unroll
        for (int nt = 0; nt < 8; nt++) {
            int col = nt * 8 + lr * 2;
            *(uint2*)&Ps[wr + lq][col]     = make_uint2(f2tf(s[nt][0]), f2tf(s[nt][1]));
            *(uint2*)&Ps[wr + lq + 8][col] = make_uint2(f2tf(s[nt][2]), f2tf(s[nt][3]));
        }
        __syncwarp();

        // O += P V  (M=16, N=64 dims, K=64 keys)
        #pragma unroll
        for (int kk = 0; kk < 8; kk++) {
            int koff = kk * 8;
            unsigned afr[4];
            afr[0] = Ps[wr + lq][koff + lr];
            afr[1] = Ps[wr + lq + 8][koff + lr];
            afr[2] = Ps[wr + lq][koff + 4 + lr];
            afr[3] = Ps[wr + lq + 8][koff + 4 + lr];
            #pragma unroll
            for (int nt = 0; nt < 8; nt++) {
                unsigned bfr[2];
                bfr[0] = Vs[koff + lr][nt * 8 + lq];
                bfr[1] = Vs[koff + 4 + lr][nt * 8 + lq];
                mma_tf32(o[nt], afr, bfr);
            }
        }
    }

    // normalize + write [B,S,H,D]
    float inv0 = 1.0f / l_i[0], inv1 = 1.0f / l_i[1];
    #pragma unroll
    for (int nt = 0; nt < 8; nt++) {
        int d = nt * 8 + lr * 2;
        size_t i0 = (((size_t)bb * S_ + q0 + wr + lq) * H_ + h) * D_ + d;
        size_t i1 = (((size_t)bb * S_ + q0 + wr + lq + 8) * H_ + h) * D_ + d;
        *(float2*)(outbuf + i0) = make_float2(o[nt][0] * inv0, o[nt][1] * inv0);
        *(float2*)(outbuf + i1) = make_float2(o[nt][2] * inv1, o[nt][3] * inv1);
    }
}

// ---------------------------------------------------------------------------
extern "C" void kernel_launch(void* const* d_in, const int* in_sizes, int n_in,
                              void* d_out, int out_size)
{
    const float* x  = (const float*)d_in[0];
    const float* Wq = (const float*)d_in[1];
    const float* bq = (const float*)d_in[2];
    const float* Wk = (const float*)d_in[3];
    const float* bk = (const float*)d_in[4];
    const float* Wv = (const float*)d_in[5];
    const float* bv = (const float*)d_in[6];
    const float* Wo = (const float*)d_in[7];
    const float* bo = (const float*)d_in[8];
    float* out = (float*)d_out;

    float *pq, *pk, *pv, *pa;
    cudaGetSymbolAddress((void**)&pq, g_q);
    cudaGetSymbolAddress((void**)&pk, g_k);
    cudaGetSymbolAddress((void**)&pv, g_v);
    cudaGetSymbolAddress((void**)&pa, g_attn);

    const int smem_attn = 4 * 64 * 68 * sizeof(unsigned);  // 69632
    cudaFuncSetAttribute(attn_tc, cudaFuncAttributeMaxDynamicSharedMemorySize, smem_attn);

    rope_table_kernel<<<(S_*D_ + 255)/256, 256>>>();

    dim3 gg(E_/128, M_/128);   // (8, 32)
    gemm_tc<1><<<gg, 256>>>(x,  Wq, bq, pq);
    gemm_tc<1><<<gg, 256>>>(x,  Wk, bk, pk);
    gemm_tc<2><<<gg, 256>>>(x,  Wv, bv, pv);
    attn_tc<<<dim3(S_/64, H_, B_), 128, smem_attn>>>(pa);
    gemm_tc<0><<<gg, 256>>>(pa, Wo, bo, out);
}

// round 3
// speedup vs baseline: 3.9967x; 1.0990x over previous
#include <cuda_runtime.h>
#include <math.h>

#define B_ 2
#define S_ 2048
#define H_ 16
#define D_ 64
#define E_ 1024
#define M_ (B_*S_)

// Scratch (allocation-free)
__device__ float g_q[B_*H_*S_*D_];
__device__ float g_k[B_*H_*S_*D_];
__device__ float g_v[B_*H_*S_*D_];
__device__ float g_attn[(size_t)B_*S_*E_];
__device__ float g_cos[S_*D_];
__device__ float g_sin[S_*D_];

// ---------------------------------------------------------------------------
__device__ __forceinline__ unsigned f2tf(float x) {
    unsigned r;
    asm("cvt.rna.tf32.f32 %0, %1;" : "=r"(r) : "f"(x));
    return r;
}

__device__ __forceinline__ void mma_tf32(float c[4], const unsigned a[4], const unsigned b[2]) {
    asm volatile(
        "mma.sync.aligned.m16n8k8.row.col.f32.tf32.tf32.f32 "
        "{%0,%1,%2,%3},{%4,%5,%6,%7},{%8,%9},{%0,%1,%2,%3};\n"
        : "+f"(c[0]), "+f"(c[1]), "+f"(c[2]), "+f"(c[3])
        : "r"(a[0]), "r"(a[1]), "r"(a[2]), "r"(a[3]), "r"(b[0]), "r"(b[1]));
}

// ---------------------------------------------------------------------------
__global__ void rope_table_kernel() {
    int idx = blockIdx.x * blockDim.x + threadIdx.x;
    if (idx >= S_ * D_) return;
    int sp = idx >> 6, d = idx & 63;
    float e = (float)(2 * (d & 31)) * (1.0f / 64.0f);
    float inv = powf(10000.0f, -e);
    float s, c;
    sincosf((float)sp * inv, &s, &c);
    g_cos[idx] = c;
    g_sin[idx] = s;
}

// ---------------------------------------------------------------------------
// tf32 TC GEMM, double-buffered smem pipeline.
// C[m,n] = sum_k A[m,k]*W[n,k] + bias[n]
// MODE 0: out[m*E+n]; MODE 1: RoPE -> [B,H,S,D]; MODE 2: -> [B,H,S,D]
// 128x128x32 tile, 256 threads (8 warps), warp tile 32x64.
// ---------------------------------------------------------------------------
template<int MODE>
__global__ __launch_bounds__(256) void gemm_tc(
    const float* __restrict__ A, const float* __restrict__ W,
    const float* __restrict__ bias, float* __restrict__ out)
{
    extern __shared__ unsigned smg[];
    unsigned (*As)[36] = (unsigned(*)[36])smg;              // [2*128][36]
    unsigned (*Bs)[36] = (unsigned(*)[36])(smg + 2*128*36); // [2*128][36]

    const int tid = threadIdx.x;
    const int lane = tid & 31, wid = tid >> 5;
    const int warp_m = wid >> 1, warp_n = wid & 1;
    const int m0 = blockIdx.y * 128, n0 = blockIdx.x * 128;
    const int lq = lane >> 2, lr = lane & 3;

    // per-thread load geometry: 4 chunks, each float4 of A and W
    const int l_row = tid >> 3;          // 0..31  (row advances by 32 per chunk)
    const int l_f   = (tid & 7) * 4;     // 0..28

    float c[2][8][4];
    #pragma unroll
    for (int mt = 0; mt < 2; mt++)
        #pragma unroll
        for (int nt = 0; nt < 8; nt++)
            #pragma unroll
            for (int i = 0; i < 4; i++) c[mt][nt][i] = 0.f;

    float4 pa[4], pb[4];

    // prologue: load k-tile 0
    #pragma unroll
    for (int it = 0; it < 4; it++) {
        int row = l_row + it * 32;
        pa[it] = *(const float4*)(A + (size_t)(m0 + row) * E_ + l_f);
        pb[it] = *(const float4*)(W + (size_t)(n0 + row) * E_ + l_f);
    }
    #pragma unroll
    for (int it = 0; it < 4; it++) {
        int row = l_row + it * 32;
        uint4 u; u.x = f2tf(pa[it].x); u.y = f2tf(pa[it].y); u.z = f2tf(pa[it].z); u.w = f2tf(pa[it].w);
        *(uint4*)&As[row][l_f] = u;
        uint4 v; v.x = f2tf(pb[it].x); v.y = f2tf(pb[it].y); v.z = f2tf(pb[it].z); v.w = f2tf(pb[it].w);
        *(uint4*)&Bs[row][l_f] = v;
    }
    __syncthreads();

    const int NKT = E_ / 32;   // 32
    for (int kt = 0; kt < NKT; kt++) {
        const int cur = (kt & 1) * 128;
        // prefetch next k-tile into registers (in flight during mma)
        if (kt + 1 < NKT) {
            int k0 = (kt + 1) * 32;
            #pragma unroll
            for (int it = 0; it < 4; it++) {
                int row = l_row + it * 32;
                pa[it] = *(const float4*)(A + (size_t)(m0 + row) * E_ + k0 + l_f);
                pb[it] = *(const float4*)(W + (size_t)(n0 + row) * E_ + k0 + l_f);
            }
        }
        // compute on current buffer
        #pragma unroll
        for (int kk = 0; kk < 4; kk++) {
            int koff = kk * 8;
            unsigned bfr[8][2];
            #pragma unroll
            for (int nt = 0; nt < 8; nt++) {
                int nc = cur + warp_n * 64 + nt * 8 + lq;
                bfr[nt][0] = Bs[nc][koff + lr];
                bfr[nt][1] = Bs[nc][koff + 4 + lr];
            }
            unsigned afr[2][4];
            #pragma unroll
            for (int mt = 0; mt < 2; mt++) {
                int mr = cur + warp_m * 32 + mt * 16 + lq;
                afr[mt][0] = As[mr][koff + lr];
                afr[mt][1] = As[mr + 8][koff + lr];
                afr[mt][2] = As[mr][koff + 4 + lr];
                afr[mt][3] = As[mr + 8][koff + 4 + lr];
            }
            #pragma unroll
            for (int mt = 0; mt < 2; mt++)
                #pragma unroll
                for (int nt = 0; nt < 8; nt++)
                    mma_tf32(c[mt][nt], afr[mt], bfr[nt]);
        }
        // store prefetched tile to the other buffer
        if (kt + 1 < NKT) {
            const int nxt = ((kt + 1) & 1) * 128;
            #pragma unroll
            for (int it = 0; it < 4; it++) {
                int row = nxt + l_row + it * 32;
                uint4 u; u.x = f2tf(pa[it].x); u.y = f2tf(pa[it].y); u.z = f2tf(pa[it].z); u.w = f2tf(pa[it].w);
                *(uint4*)&As[row][l_f] = u;
                uint4 v; v.x = f2tf(pb[it].x); v.y = f2tf(pb[it].y); v.z = f2tf(pb[it].z); v.w = f2tf(pb[it].w);
                *(uint4*)&Bs[row][l_f] = v;
            }
            __syncthreads();
        }
    }

    // epilogue
    #pragma unroll
    for (int mt = 0; mt < 2; mt++) {
        #pragma unroll
        for (int rh = 0; rh < 2; rh++) {
            int m = m0 + warp_m * 32 + mt * 16 + lq + rh * 8;
            int bb = m >> 11, sp = m & (S_ - 1);
            #pragma unroll
            for (int nt = 0; nt < 8; nt++) {
                int n = n0 + warp_n * 64 + nt * 8 + lr * 2;
                float2 bi = *(const float2*)(bias + n);
                float v0 = c[mt][nt][rh * 2]     + bi.x;
                float v1 = c[mt][nt][rh * 2 + 1] + bi.y;
                if (MODE == 0) {
                    *(float2*)(out + (size_t)m * E_ + n) = make_float2(v0, v1);
                } else {
                    int h = n >> 6, d = n & 63;
                    float o0 = v0, o1 = v1;
                    if (MODE == 1) {
                        float2 cs = *(const float2*)(g_cos + sp * D_ + d);
                        float2 sn = *(const float2*)(g_sin + sp * D_ + d);
                        o0 = v0 * cs.x - v1 * sn.x;
                        o1 = v1 * cs.y + v0 * sn.y;
                    }
                    size_t base = (((size_t)(bb * H_ + h)) * S_ + sp) * D_ + d;
                    *(float2*)(out + base) = make_float2(o0, o1);
                }
            }
        }
    }
}

// ---------------------------------------------------------------------------
// Flash attention, tf32 mma. 128 threads (4 warps), Q tile 64 rows.
// Q fragments hoisted to registers (pre-scaled by 1/8). Qs smem reused as Ps.
// ---------------------------------------------------------------------------
__global__ __launch_bounds__(128) void attn_tc(float* __restrict__ outbuf)
{
    extern __shared__ unsigned smu[];
    unsigned (*Ks)[68] = (unsigned(*)[68])smu;
    unsigned (*Vs)[68] = (unsigned(*)[68])(smu + 64*68);
    unsigned (*Ps)[68] = (unsigned(*)[68])(smu + 2*64*68);  // also Q staging

    const int tid = threadIdx.x;
    const int lane = tid & 31, wid = tid >> 5;
    const int lq = lane >> 2, lr = lane & 3;
    const int wr = wid * 16;
    const int q0 = blockIdx.x * 64;
    const int h = blockIdx.y, bb = blockIdx.z;
    const size_t head_base = ((size_t)(bb * H_ + h)) * S_ * D_;

    // stage Q tile into smem (scaled by 1/8), then extract fragments to regs
    #pragma unroll
    for (int it = 0; it < 4; it++) {
        int id = tid + it * 128;
        int row = id >> 3, f = (id & 7) * 4;   // wait: 64 rows x 16 float4 = 1024 chunks/... 
        (void)row; (void)f;
    }
    // 64 rows x 64 floats = 1024 float4 loads? no: 64*64/4 = 1024 float4; 128 thr x 8 it
    #pragma unroll
    for (int it = 0; it < 8; it++) {
        int id = tid + it * 128;
        int row = id >> 4, f = (id & 15) * 4;
        float4 v = *(const float4*)(g_q + head_base + (size_t)(q0 + row) * D_ + f);
        uint4 u;
        u.x = f2tf(v.x * 0.125f); u.y = f2tf(v.y * 0.125f);
        u.z = f2tf(v.z * 0.125f); u.w = f2tf(v.w * 0.125f);
        *(uint4*)&Ps[row][f] = u;
    }
    __syncthreads();

    unsigned qfr[8][4];
    #pragma unroll
    for (int kk = 0; kk < 8; kk++) {
        int koff = kk * 8;
        qfr[kk][0] = Ps[wr + lq][koff + lr];
        qfr[kk][1] = Ps[wr + lq + 8][koff + lr];
        qfr[kk][2] = Ps[wr + lq][koff + 4 + lr];
        qfr[kk][3] = Ps[wr + lq + 8][koff + 4 + lr];
    }
    // note: from here on, Ps rows [wr, wr+16) are touched only by this warp.

    float o[8][4];
    float m_i[2] = {-1e30f, -1e30f}, l_i[2] = {0.f, 0.f};
    #pragma unroll
    for (int nt = 0; nt < 8; nt++)
        #pragma unroll
        for (int i = 0; i < 4; i++) o[nt][i] = 0.f;

    for (int kt = 0; kt < S_; kt += 64) {
        __syncthreads();
        #pragma unroll
        for (int it = 0; it < 8; it++) {
            int id = tid + it * 128;
            int row = id >> 4, f = (id & 15) * 4;
            float4 kv = *(const float4*)(g_k + head_base + (size_t)(kt + row) * D_ + f);
            uint4 u;
            u.x = f2tf(kv.x); u.y = f2tf(kv.y); u.z = f2tf(kv.z); u.w = f2tf(kv.w);
            *(uint4*)&Ks[row][f] = u;
            float4 vv = *(const float4*)(g_v + head_base + (size_t)(kt + row) * D_ + f);
            uint4 w;
            w.x = f2tf(vv.x); w.y = f2tf(vv.y); w.z = f2tf(vv.z); w.w = f2tf(vv.w);
            *(uint4*)&Vs[row][f] = w;
        }
        __syncthreads();

        // S = (Q/8) K^T
        float s[8][4];
        #pragma unroll
        for (int nt = 0; nt < 8; nt++)
            #pragma unroll
            for (int i = 0; i < 4; i++) s[nt][i] = 0.f;

        #pragma unroll
        for (int kk = 0; kk < 8; kk++) {
            int koff = kk * 8;
            #pragma unroll
            for (int nt = 0; nt < 8; nt++) {
                unsigned bfr[2];
                bfr[0] = Ks[nt * 8 + lq][koff + lr];
                bfr[1] = Ks[nt * 8 + lq][koff + 4 + lr];
                mma_tf32(s[nt], qfr[kk], bfr);
            }
        }

        // online softmax (rows: lq -> c0/c1, lq+8 -> c2/c3)
        #pragma unroll
        for (int rh = 0; rh < 2; rh++) {
            float mx = -1e30f;
            #pragma unroll
            for (int nt = 0; nt < 8; nt++)
                mx = fmaxf(mx, fmaxf(s[nt][rh*2], s[nt][rh*2+1]));
            mx = fmaxf(mx, __shfl_xor_sync(0xffffffffu, mx, 1));
            mx = fmaxf(mx, __shfl_xor_sync(0xffffffffu, mx, 2));
            float mnew = fmaxf(m_i[rh], mx);
            float corr = __expf(m_i[rh] - mnew);
            m_i[rh] = mnew;
            float sum = 0.f;
            #pragma unroll
            for (int nt = 0; nt < 8; nt++) {
                float p0 = __expf(s[nt][rh*2]   - mnew);
                float p1 = __expf(s[nt][rh*2+1] - mnew);
                s[nt][rh*2] = p0; s[nt][rh*2+1] = p1;
                sum += p0 + p1;
            }
            sum += __shfl_xor_sync(0xffffffffu, sum, 1);
            sum += __shfl_xor_sync(0xffffffffu, sum, 2);
            l_i[rh] = l_i[rh] * corr + sum;
            #pragma unroll
            for (int nt = 0; nt < 8; nt++) {
                o[nt][rh*2]   *= corr;
                o[nt][rh*2+1] *= corr;
            }
        }

        // P -> smem (warp-private rows)
        #pragma unroll
        for (int nt = 0; nt < 8; nt++) {
            int col = nt * 8 + lr * 2;
            *(uint2*)&Ps[wr + lq][col]     = make_uint2(f2tf(s[nt][0]), f2tf(s[nt][1]));
            *(uint2*)&Ps[wr + lq + 8][col] = make_uint2(f2tf(s[nt][2]), f2tf(s[nt][3]));
        }
        __syncwarp();

        // O += P V
        #pragma unroll
        for (int kk = 0; kk < 8; kk++) {
            int koff = kk * 8;
            unsigned afr[4];
            afr[0] = Ps[wr + lq][koff + lr];
            afr[1] = Ps[wr + lq + 8][koff + lr];
            afr[2] = Ps[wr + lq][koff + 4 + lr];
            afr[3] = Ps[wr + lq + 8][koff + 4 + lr];
            #pragma unroll
            for (int nt = 0; nt < 8; nt++) {
                unsigned bfr[2];
                bfr[0] = Vs[koff + lr][nt * 8 + lq];
                bfr[1] = Vs[koff + 4 + lr][nt * 8 + lq];
                mma_tf32(o[nt], afr, bfr);
            }
        }
    }

    // normalize + write [B,S,H,D]
    float inv0 = 1.0f / l_i[0], inv1 = 1.0f / l_i[1];
    #pragma unroll
    for (int nt = 0; nt < 8; nt++) {
        int d = nt * 8 + lr * 2;
        size_t i0 = (((size_t)bb * S_ + q0 + wr + lq) * H_ + h) * D_ + d;
        size_t i1 = (((size_t)bb * S_ + q0 + wr + lq + 8) * H_ + h) * D_ + d;
        *(float2*)(outbuf + i0) = make_float2(o[nt][0] * inv0, o[nt][1] * inv0);
        *(float2*)(outbuf + i1) = make_float2(o[nt][2] * inv1, o[nt][3] * inv1);
    }
}

// ---------------------------------------------------------------------------
extern "C" void kernel_launch(void* const* d_in, const int* in_sizes, int n_in,
                              void* d_out, int out_size)
{
    const float* x  = (const float*)d_in[0];
    const float* Wq = (const float*)d_in[1];
    const float* bq = (const float*)d_in[2];
    const float* Wk = (const float*)d_in[3];
    const float* bk = (const float*)d_in[4];
    const float* Wv = (const float*)d_in[5];
    const float* bv = (const float*)d_in[6];
    const float* Wo = (const float*)d_in[7];
    const float* bo = (const float*)d_in[8];
    float* out = (float*)d_out;

    float *pq, *pk, *pv, *pa;
    cudaGetSymbolAddress((void**)&pq, g_q);
    cudaGetSymbolAddress((void**)&pk, g_k);
    cudaGetSymbolAddress((void**)&pv, g_v);
    cudaGetSymbolAddress((void**)&pa, g_attn);

    const int smem_gemm = 2 * 2 * 128 * 36 * sizeof(unsigned);  // 73728
    const int smem_attn = 3 * 64 * 68 * sizeof(unsigned);       // 52224
    cudaFuncSetAttribute(gemm_tc<0>, cudaFuncAttributeMaxDynamicSharedMemorySize, smem_gemm);
    cudaFuncSetAttribute(gemm_tc<1>, cudaFuncAttributeMaxDynamicSharedMemorySize, smem_gemm);
    cudaFuncSetAttribute(gemm_tc<2>, cudaFuncAttributeMaxDynamicSharedMemorySize, smem_gemm);
    cudaFuncSetAttribute(attn_tc,    cudaFuncAttributeMaxDynamicSharedMemorySize, smem_attn);

    rope_table_kernel<<<(S_*D_ + 255)/256, 256>>>();

    dim3 gg(E_/128, M_/128);   // (8, 32)
    gemm_tc<1><<<gg, 256, smem_gemm>>>(x,  Wq, bq, pq);
    gemm_tc<1><<<gg, 256, smem_gemm>>>(x,  Wk, bk, pk);
    gemm_tc<2><<<gg, 256, smem_gemm>>>(x,  Wv, bv, pv);
    attn_tc<<<dim3(S_/64, H_, B_), 128, smem_attn>>>(pa);
    gemm_tc<0><<<gg, 256, smem_gemm>>>(pa, Wo, bo, out);
}